// round 10
// baseline (speedup 1.0000x reference)
#include <cuda_runtime.h>
#include <cstdint>
#include <math.h>

#define BB 16
#define NN 1024
#define CC 256

// ---------------- scratch (__device__ globals: allocation-free) ----------------
__device__ float    g_Wp[CC];             // W @ pooling  (row dots)
__device__ float    g_scal[2];            // [0] = 1/||p||, [1] = b.p
__device__ float    g_t[BB * NN];         // x . Wp  per node
__device__ float    g_y[BB * NN];         // scores
__device__ float    g_mf[BB * NN];        // new mask (float)
__device__ unsigned g_bits[(size_t)BB * NN * 32];  // adjacency bitmaps (2 MB)
__device__ int      g_rows[BB * NN];      // compacted surviving node ids per batch
__device__ int      g_dead[BB * NN];      // compacted dead node ids per batch
__device__ int      g_nrows[BB];          // surviving count per batch
__device__ int      g_ndead[BB];          // dead count per batch
__device__ float    g_gc[(size_t)BB * NN * CC];    // gathered sums, compact (16 MB)

// ---------------- tf32 split helpers ----------------
__device__ __forceinline__ void tf32split(float v, float& hi, float& lo) {
    unsigned h;
    asm("cvt.rna.tf32.f32 %0, %1;" : "=r"(h) : "f"(v));
    hi = __uint_as_float(h);
    float l = v - hi;              // exact in fp32 (<=14 significant bits)
    unsigned h2;
    asm("cvt.rna.tf32.f32 %0, %1;" : "=r"(h2) : "f"(l));
    lo = __uint_as_float(h2);
}

#define MMA_TF32(d, a, b)                                                       \
    asm volatile(                                                               \
        "mma.sync.aligned.m16n8k8.row.col.f32.tf32.tf32.f32 "                   \
        "{%0,%1,%2,%3},{%4,%5,%6,%7},{%8,%9},{%0,%1,%2,%3};"                    \
        : "+f"((d)[0]), "+f"((d)[1]), "+f"((d)[2]), "+f"((d)[3])                \
        : "r"((a)[0]), "r"((a)[1]), "r"((a)[2]), "r"((a)[3]),                   \
          "r"((b)[0]), "r"((b)[1]))

// ---------------- K_prep: blocks 0..31: Wp rows; block 32: scal ----------------
__global__ void k_prep(const float* __restrict__ W,
                       const float* __restrict__ b,
                       const float* __restrict__ p) {
    int tid = threadIdx.x;  // 256
    if (blockIdx.x == 32) {
        __shared__ float s1[CC], s2[CC];
        float pc = p[tid];
        s1[tid] = pc * pc;
        s2[tid] = b[tid] * pc;
        __syncthreads();
        for (int off = CC / 2; off > 0; off >>= 1) {
            if (tid < off) { s1[tid] += s1[tid + off]; s2[tid] += s2[tid + off]; }
            __syncthreads();
        }
        if (tid == 0) {
            g_scal[0] = 1.0f / sqrtf(s1[0]);
            g_scal[1] = s2[0];
        }
        return;
    }
    __shared__ float ps[CC];
    ps[tid] = p[tid];
    __syncthreads();
    int warp = tid >> 5, lane = tid & 31;
    int r = blockIdx.x * 8 + warp;
    const float* wr = W + (size_t)r * CC;
    float acc = 0.f;
#pragma unroll
    for (int j = lane; j < CC; j += 32) acc += wr[j] * ps[j];
    for (int o = 16; o > 0; o >>= 1) acc += __shfl_down_sync(0xffffffffu, acc, o);
    if (lane == 0) g_Wp[r] = acc;
}

// ---------------- K_t: t[b,n] = x[b,n,:] . Wp  (warp per row, float4) ----------------
__global__ void k_t(const float* __restrict__ x) {
    __shared__ float4 wp4[CC / 4];
    int tid = threadIdx.x;  // 256
    if (tid < CC / 4) wp4[tid] = ((const float4*)g_Wp)[tid];
    __syncthreads();
    int warp = tid >> 5, lane = tid & 31;
    int row = blockIdx.x * 8 + warp;           // [0, BB*NN)
    const float4* xr = (const float4*)(x + (size_t)row * CC);
    float4 v0 = xr[lane];
    float4 v1 = xr[lane + 32];
    float4 w0 = wp4[lane];
    float4 w1 = wp4[lane + 32];
    float acc = v0.x * w0.x + v0.y * w0.y + v0.z * w0.z + v0.w * w0.w
              + v1.x * w1.x + v1.y * w1.y + v1.z * w1.z + v1.w * w1.w;
    for (int o = 16; o > 0; o >>= 1) acc += __shfl_down_sync(0xffffffffu, acc, o);
    if (lane == 0) g_t[row] = acc;
}

// ---------------- K_bits: adj -> row bitmaps (no score; no deps) ----------------
// Bit layout: column = chunk*128 + 4*bitpos + u  for word u (0..3) of chunk (0..7).
__global__ void k_bits(const float* __restrict__ adj) {
    int tid = threadIdx.x;             // 256
    int b = blockIdx.x >> 7;           // 128 blocks per batch
    int chunk = blockIdx.x & 127;
    int warp = tid >> 5, lane = tid & 31;
    int n = chunk * 8 + warp;
    const float* ar = adj + ((size_t)b * NN + n) * NN;
    uint4* br = (uint4*)(g_bits + ((size_t)(b * NN) + n) * 32);
#pragma unroll
    for (int c = 0; c < 8; c++) {
        float4 v = *(const float4*)(ar + c * 128 + lane * 4);
        unsigned b0 = __ballot_sync(0xffffffffu, v.x != 0.0f);
        unsigned b1 = __ballot_sync(0xffffffffu, v.y != 0.0f);
        unsigned b2 = __ballot_sync(0xffffffffu, v.z != 0.0f);
        unsigned b3 = __ballot_sync(0xffffffffu, v.w != 0.0f);
        if (lane == 0) br[c] = make_uint4(b0, b1, b2, b3);
    }
}

// ---------------- K_y: y[b,n] = sum_{j in row bitmap} t[b,j], scaled ----------------
__global__ void k_y() {
    int b = blockIdx.x;
    int t = threadIdx.x;               // 1024
    __shared__ float st[NN];
    st[t] = g_t[b * NN + t];
    __syncthreads();
    const uint4* bw = (const uint4*)(g_bits + ((size_t)(b * NN) + t) * 32);
    float acc = 0.f;
#pragma unroll
    for (int c = 0; c < 8; c++) {
        uint4 v = bw[c];
        unsigned ws[4] = {v.x, v.y, v.z, v.w};
#pragma unroll
        for (int u = 0; u < 4; u++) {
            unsigned w = ws[u];
            while (w) {
                int L = __ffs(w) - 1;
                w &= w - 1;
                acc += st[c * 128 + 4 * L + u];
            }
        }
    }
    g_y[b * NN + t] = (acc + g_scal[1]) * g_scal[0];
}

// ---------------- K_rank: u64 keys, 16 subs per i (grid 16x16, one full wave) ----------------
__global__ void k_rank(const int* __restrict__ mask,
                       const int* __restrict__ n_nodes,
                       float* __restrict__ out_mask) {
    int b = blockIdx.y;
    __shared__ unsigned long long ks[NN];
    int t = threadIdx.x;               // 1024
    int mt = mask[b * NN + t];
    float yv = g_y[b * NN + t];
    unsigned u = __float_as_uint(yv);
    u = (u & 0x80000000u) ? ~u : (u | 0x80000000u);  // monotone float->uint
    ks[t] = mt ? ((((unsigned long long)u) << 10) | (unsigned)t)
               : 0xFFFFFFFFFFFFFFFFull;
    __syncthreads();
    int i   = blockIdx.x * 64 + (t >> 4);
    int sub = t & 15;
    unsigned long long ki = ks[i];
    const ulonglong2* ks2 = (const ulonglong2*)ks;
    int r = 0;
#pragma unroll 8
    for (int k = 0; k < 32; k++) {
        ulonglong2 v = ks2[sub + 16 * k];
        r += (v.x < ki) ? 1 : 0;
        r += (v.y < ki) ? 1 : 0;
    }
    r += __shfl_down_sync(0xffffffffu, r, 8, 16);
    r += __shfl_down_sync(0xffffffffu, r, 4, 16);
    r += __shfl_down_sync(0xffffffffu, r, 2, 16);
    r += __shfl_down_sync(0xffffffffu, r, 1, 16);
    if (sub == 0) {
        int mi = mask[b * NN + i];
        int nrem = (int)((float)n_nodes[b] * 0.5f);   // (1 - POOL_RATIO)
        int nm = (mi != 0 && r >= nrem) ? 1 : 0;
        g_mf[b * NN + i] = (float)nm;
        out_mask[b * NN + i] = (float)nm;
    }
}

// ---------------- K_compact: warp-scan -> live list + dead list ----------------
__global__ void k_compact(const int* __restrict__ n_nodes, float* __restrict__ out_nn) {
    int b = blockIdx.x;
    int i = threadIdx.x;               // 1024
    int lane = i & 31, w = i >> 5;
    int nm = (int)g_mf[b * NN + i];
    unsigned ball = __ballot_sync(0xffffffffu, nm != 0);
    int wpre = __popc(ball & ((1u << lane) - 1u));
    __shared__ int wsum[32];
    if (lane == 0) wsum[w] = __popc(ball);
    __syncthreads();
    if (w == 0) {
        int orig = wsum[lane];
        int v = orig;
        for (int o = 1; o < 32; o <<= 1) {
            int u = __shfl_up_sync(0xffffffffu, v, o);
            if (lane >= o) v += u;
        }
        wsum[lane] = v - orig;   // exclusive
    }
    __syncthreads();
    int excl = wsum[w] + wpre;
    if (nm) g_rows[b * NN + excl] = i;
    else    g_dead[b * NN + (i - excl)] = i;
    if (i == NN - 1) {
        int tot = excl + nm;
        g_nrows[b] = tot;
        g_ndead[b] = NN - tot;
        int nrem = (int)((float)n_nodes[b] * 0.5f);
        out_nn[b] = (float)(n_nodes[b] - nrem);
    }
}

// ---------------- K_gather: per-row bitmap decoded ONCE to smem indices ----------------
__global__ __launch_bounds__(256) void k_gather(const float* __restrict__ x) {
    int b = blockIdx.y;
    int nrows = g_nrows[b];
    if (blockIdx.x * 4 >= nrows) return;
    int tid = threadIdx.x;
    int sub = tid >> 6;        // row within block
    int ct  = tid & 63;        // float4 channel group
    int pos = blockIdx.x * 4 + sub;
    bool active = pos < nrows;

    __shared__ unsigned short sidx[4][256];
    __shared__ int scnt[4];

    // decode: first warp of each row group (ct<32), one bitmap word per lane
    if (active && ct < 32) {
        int row = g_rows[b * NN + pos];
        unsigned w = g_bits[((size_t)(b * NN) + row) * 32 + ct];
        int cnt = __popc(w);
        int inc = cnt;
        for (int o = 1; o < 32; o <<= 1) {
            int v = __shfl_up_sync(0xffffffffu, inc, o);
            if (ct >= o) inc += v;
        }
        int start = inc - cnt;
        int base = (ct >> 2) * 128 + (ct & 3);
        while (w) {
            int L = __ffs(w) - 1;
            w &= w - 1;
            sidx[sub][start++] = (unsigned short)(base + 4 * L);
        }
        if (ct == 31) scnt[sub] = inc;
    }
    __syncthreads();
    if (!active) return;

    int cnt = scnt[sub];
    const float* xb = x + (size_t)b * NN * CC + ct * 4;
    float4 a0 = make_float4(0.f, 0.f, 0.f, 0.f);
    float4 a1 = make_float4(0.f, 0.f, 0.f, 0.f);
    float4 a2 = make_float4(0.f, 0.f, 0.f, 0.f);
    float4 a3 = make_float4(0.f, 0.f, 0.f, 0.f);
    int t = 0;
    for (; t + 4 <= cnt; t += 4) {
        float4 v0 = *(const float4*)(xb + (int)sidx[sub][t] * CC);
        float4 v1 = *(const float4*)(xb + (int)sidx[sub][t + 1] * CC);
        float4 v2 = *(const float4*)(xb + (int)sidx[sub][t + 2] * CC);
        float4 v3 = *(const float4*)(xb + (int)sidx[sub][t + 3] * CC);
        a0.x += v0.x; a0.y += v0.y; a0.z += v0.z; a0.w += v0.w;
        a1.x += v1.x; a1.y += v1.y; a1.z += v1.z; a1.w += v1.w;
        a2.x += v2.x; a2.y += v2.y; a2.z += v2.z; a2.w += v2.w;
        a3.x += v3.x; a3.y += v3.y; a3.z += v3.z; a3.w += v3.w;
    }
    for (; t < cnt; t++) {
        float4 v = *(const float4*)(xb + (int)sidx[sub][t] * CC);
        a0.x += v.x; a0.y += v.y; a0.z += v.z; a0.w += v.w;
    }
    float4 r;
    r.x = (a0.x + a1.x) + (a2.x + a3.x);
    r.y = (a0.y + a1.y) + (a2.y + a3.y);
    r.z = (a0.z + a1.z) + (a2.z + a3.z);
    r.w = (a0.w + a1.w) + (a2.w + a3.w);
    *(float4*)(g_gc + ((size_t)b * NN + pos) * CC + ct * 4) = r;
}

// ---------------- K_gemm: tf32 MMA, 3-term split, dead-row zeroing folded in ----------------
#define GM 128
#define GN 128
#define GK 16
#define AP 20    // A-tile k pitch (floats): conflict-free fragment loads
#define BPD 136  // B-tile n pitch

__global__ __launch_bounds__(256) void k_gemm(const float* __restrict__ W,
                                              const float* __restrict__ bvec,
                                              float* __restrict__ out_x) {
    __shared__ float Ah[GM][AP], Al[GM][AP];
    __shared__ float Bh[GK][BPD], Bl[GK][BPD];
    __shared__ float bs[GN];
    int b = blockIdx.z;
    int nrows = g_nrows[b];
    int row0 = blockIdx.x * GM;
    int col0 = blockIdx.y * GN;
    int tid = threadIdx.x;
    int lane = tid & 31, warp = tid >> 5;
    int wm = warp & 3, wn = warp >> 2;       // 4 M-warps x 2 N-warps
    int gid = lane >> 2, tig = lane & 3;

    if (tid < GN) bs[tid] = bvec[col0 + tid];

    float acc[2][8][4];
#pragma unroll
    for (int i = 0; i < 2; i++)
#pragma unroll
        for (int j = 0; j < 8; j++)
#pragma unroll
            for (int k = 0; k < 4; k++) acc[i][j][k] = 0.f;

    if (row0 < nrows) {
        int rows_in = nrows - row0; if (rows_in > GM) rows_in = GM;
        const float* A = g_gc + ((size_t)b * NN + row0) * CC;
        for (int kt = 0; kt < CC; kt += GK) {
#pragma unroll
            for (int u = 0; u < 2; u++) {
                int idx = tid + u * 256;
                int m = idx >> 2, k4 = idx & 3;
                float4 v = (m < rows_in)
                               ? *(const float4*)(A + (size_t)m * CC + kt + k4 * 4)
                               : make_float4(0.f, 0.f, 0.f, 0.f);
                float4 h4, l4;
                tf32split(v.x, h4.x, l4.x);
                tf32split(v.y, h4.y, l4.y);
                tf32split(v.z, h4.z, l4.z);
                tf32split(v.w, h4.w, l4.w);
                *(float4*)&Ah[m][k4 * 4] = h4;
                *(float4*)&Al[m][k4 * 4] = l4;
                int k = idx >> 5, c4 = idx & 31;
                float4 w = *(const float4*)(W + (size_t)(kt + k) * CC + col0 + c4 * 4);
                tf32split(w.x, h4.x, l4.x);
                tf32split(w.y, h4.y, l4.y);
                tf32split(w.z, h4.z, l4.z);
                tf32split(w.w, h4.w, l4.w);
                *(float4*)&Bh[k][c4 * 4] = h4;
                *(float4*)&Bl[k][c4 * 4] = l4;
            }
            __syncthreads();
#pragma unroll
            for (int k8 = 0; k8 < GK; k8 += 8) {
                unsigned ah[2][4], al[2][4], bh[8][2], bl[8][2];
#pragma unroll
                for (int mt = 0; mt < 2; mt++) {
                    int r = wm * 32 + mt * 16 + gid;
                    ah[mt][0] = __float_as_uint(Ah[r][k8 + tig]);
                    ah[mt][1] = __float_as_uint(Ah[r + 8][k8 + tig]);
                    ah[mt][2] = __float_as_uint(Ah[r][k8 + tig + 4]);
                    ah[mt][3] = __float_as_uint(Ah[r + 8][k8 + tig + 4]);
                    al[mt][0] = __float_as_uint(Al[r][k8 + tig]);
                    al[mt][1] = __float_as_uint(Al[r + 8][k8 + tig]);
                    al[mt][2] = __float_as_uint(Al[r][k8 + tig + 4]);
                    al[mt][3] = __float_as_uint(Al[r + 8][k8 + tig + 4]);
                }
#pragma unroll
                for (int nt = 0; nt < 8; nt++) {
                    int c = wn * 64 + nt * 8 + gid;
                    bh[nt][0] = __float_as_uint(Bh[k8 + tig][c]);
                    bh[nt][1] = __float_as_uint(Bh[k8 + tig + 4][c]);
                    bl[nt][0] = __float_as_uint(Bl[k8 + tig][c]);
                    bl[nt][1] = __float_as_uint(Bl[k8 + tig + 4][c]);
                }
#pragma unroll
                for (int mt = 0; mt < 2; mt++)
#pragma unroll
                    for (int nt = 0; nt < 8; nt++) {
                        MMA_TF32(acc[mt][nt], al[mt], bh[nt]);
                        MMA_TF32(acc[mt][nt], ah[mt], bl[nt]);
                        MMA_TF32(acc[mt][nt], ah[mt], bh[nt]);
                    }
            }
            __syncthreads();
        }
    }
    __syncthreads();   // bs visible for all paths (uniform)

#pragma unroll
    for (int mt = 0; mt < 2; mt++)
#pragma unroll
        for (int rh = 0; rh < 2; rh++) {
            int g = row0 + wm * 32 + mt * 16 + rh * 8 + gid;
            bool live = g < nrows;
            int node = live ? g_rows[b * NN + g] : g_dead[b * NN + g - nrows];
            float tval = live ? tanhf(g_y[b * NN + node]) : 0.f;
            float* orow = out_x + ((size_t)b * NN + node) * CC + col0 + wn * 64 + 2 * tig;
#pragma unroll
            for (int nt = 0; nt < 8; nt++) {
                float2 o;
                if (live) {
                    int c = wn * 64 + nt * 8 + 2 * tig;
                    o.x = (acc[mt][nt][rh * 2]     + bs[c])     * tval;
                    o.y = (acc[mt][nt][rh * 2 + 1] + bs[c + 1]) * tval;
                } else {
                    o.x = 0.f; o.y = 0.f;
                }
                *(float2*)(orow + nt * 8) = o;
            }
        }
}

// ---------------- K_adjout: dense bitmap expansion, 8 rows/block, full 1024 cols ----------------
__global__ __launch_bounds__(512) void k_adjout(float* __restrict__ out_adj) {
    int b = blockIdx.y;
    int tid = threadIdx.x;   // 512
    __shared__ float smf[NN];
    if (tid < 256) ((float4*)smf)[tid] = ((const float4*)(g_mf + b * NN))[tid];
    __syncthreads();
    int sub = tid >> 6, ct = tid & 63;
    int n = blockIdx.x * 8 + sub;
    float mfn = smf[n];
    const uint4* bwp = (const uint4*)(g_bits + ((size_t)(b * NN) + n) * 32);
    float4* orow = (float4*)(out_adj + ((size_t)b * NN + n) * NN);
#pragma unroll
    for (int u2 = 0; u2 < 4; u2++) {
        int cg = ct + u2 * 64;             // float4 column group 0..255
        uint4 bw = bwp[cg >> 5];           // chunk cg>>5 (0..7), words u0..u3
        int L = cg & 31;
        float4 mrow = ((const float4*)smf)[cg];   // mf for cols 4cg..4cg+3
        float4 o;
        o.x = ((bw.x >> L) & 1u) ? mfn * mrow.x : 0.f;
        o.y = ((bw.y >> L) & 1u) ? mfn * mrow.y : 0.f;
        o.z = ((bw.z >> L) & 1u) ? mfn * mrow.z : 0.f;
        o.w = ((bw.w >> L) & 1u) ? mfn * mrow.w : 0.f;
        orow[cg] = o;
    }
}

// ---------------- launch ----------------
extern "C" void kernel_launch(void* const* d_in, const int* in_sizes, int n_in,
                              void* d_out, int out_size) {
    const float* x    = (const float*)d_in[0];  // [B,N,C]
    const float* adj  = (const float*)d_in[1];  // [B,N,N]
    const int*   mask = (const int*)d_in[2];    // [B,N]
    const int*   nnod = (const int*)d_in[3];    // [B]
    const float* W    = (const float*)d_in[4];  // [C,C]
    const float* bv   = (const float*)d_in[5];  // [C]
    const float* pool = (const float*)d_in[6];  // [C,1]

    float* out = (float*)d_out;
    float* out_x    = out;                                   // B*N*C
    float* out_adj  = out + (size_t)BB * NN * CC;            // B*N*N
    float* out_mask = out_adj + (size_t)BB * NN * NN;        // B*N
    float* out_nn   = out_mask + (size_t)BB * NN;            // B

    // side stream + events (host-side resources only)
    cudaStream_t s2;
    cudaEvent_t e0, eT, eR, eJ;
    cudaStreamCreateWithFlags(&s2, cudaStreamNonBlocking);
    cudaEventCreateWithFlags(&e0, cudaEventDisableTiming);
    cudaEventCreateWithFlags(&eT, cudaEventDisableTiming);
    cudaEventCreateWithFlags(&eR, cudaEventDisableTiming);
    cudaEventCreateWithFlags(&eJ, cudaEventDisableTiming);

    // fork at t=0: s2 runs prep -> k_t while main runs the heavy k_bits
    cudaEventRecord(e0, 0);
    cudaStreamWaitEvent(s2, e0, 0);
    k_prep<<<33, 256, 0, s2>>>(W, bv, pool);
    k_t<<<(BB * NN) / 8, 256, 0, s2>>>(x);
    cudaEventRecord(eT, s2);

    k_bits<<<(BB * NN) / 8, 256>>>(adj);

    cudaStreamWaitEvent(0, eT, 0);   // join: k_y needs g_t, g_scal, g_bits
    k_y<<<BB, 1024>>>();
    k_rank<<<dim3(16, BB), 1024>>>(mask, nnod, out_mask);

    // fork: adjout needs only g_mf (rank) + g_bits
    cudaEventRecord(eR, 0);
    cudaStreamWaitEvent(s2, eR, 0);
    k_adjout<<<dim3(NN / 8, BB), 512, 0, s2>>>(out_adj);
    cudaEventRecord(eJ, s2);

    k_compact<<<BB, 1024>>>(nnod, out_nn);
    k_gather<<<dim3(NN / 4, BB), 256>>>(x);
    k_gemm<<<dim3(NN / GM, CC / GN, BB), 256>>>(W, bv, out_x);

    // join
    cudaStreamWaitEvent(0, eJ, 0);
}

// round 11
// speedup vs baseline: 1.0569x; 1.0569x over previous
#include <cuda_runtime.h>
#include <cstdint>
#include <math.h>

#define BB 16
#define NN 1024
#define CC 256

// ---------------- scratch (__device__ globals: allocation-free) ----------------
__device__ float    g_Wp[CC];             // W @ pooling  (row dots)
__device__ float    g_scal[2];            // [0] = 1/||p||, [1] = b.p
__device__ float    g_t[BB * NN];         // x . Wp  per node
__device__ float    g_y[BB * NN];         // scores
__device__ float    g_mf[BB * NN];        // new mask (float)
__device__ unsigned g_bits[(size_t)BB * NN * 32];  // adjacency bitmaps (2 MB)
__device__ int      g_rows[BB * NN];      // compacted surviving node ids per batch
__device__ int      g_dead[BB * NN];      // compacted dead node ids per batch
__device__ int      g_nrows[BB];          // surviving count per batch
__device__ int      g_ndead[BB];          // dead count per batch
__device__ float    g_gc[(size_t)BB * NN * CC];    // gathered sums, compact (16 MB)

// ---------------- tf32 split helpers ----------------
__device__ __forceinline__ void tf32split(float v, float& hi, float& lo) {
    unsigned h;
    asm("cvt.rna.tf32.f32 %0, %1;" : "=r"(h) : "f"(v));
    hi = __uint_as_float(h);
    float l = v - hi;              // exact in fp32 (<=14 significant bits)
    unsigned h2;
    asm("cvt.rna.tf32.f32 %0, %1;" : "=r"(h2) : "f"(l));
    lo = __uint_as_float(h2);
}

#define MMA_TF32(d, a, b)                                                       \
    asm volatile(                                                               \
        "mma.sync.aligned.m16n8k8.row.col.f32.tf32.tf32.f32 "                   \
        "{%0,%1,%2,%3},{%4,%5,%6,%7},{%8,%9},{%0,%1,%2,%3};"                    \
        : "+f"((d)[0]), "+f"((d)[1]), "+f"((d)[2]), "+f"((d)[3])                \
        : "r"((a)[0]), "r"((a)[1]), "r"((a)[2]), "r"((a)[3]),                   \
          "r"((b)[0]), "r"((b)[1]))

// ---------------- K_prep: blocks 0..31: Wp rows; block 32: scal ----------------
__global__ void k_prep(const float* __restrict__ W,
                       const float* __restrict__ b,
                       const float* __restrict__ p) {
    int tid = threadIdx.x;  // 256
    if (blockIdx.x == 32) {
        __shared__ float s1[CC], s2[CC];
        float pc = p[tid];
        s1[tid] = pc * pc;
        s2[tid] = b[tid] * pc;
        __syncthreads();
        for (int off = CC / 2; off > 0; off >>= 1) {
            if (tid < off) { s1[tid] += s1[tid + off]; s2[tid] += s2[tid + off]; }
            __syncthreads();
        }
        if (tid == 0) {
            g_scal[0] = 1.0f / sqrtf(s1[0]);
            g_scal[1] = s2[0];
        }
        return;
    }
    __shared__ float ps[CC];
    ps[tid] = p[tid];
    __syncthreads();
    int warp = tid >> 5, lane = tid & 31;
    int r = blockIdx.x * 8 + warp;
    const float* wr = W + (size_t)r * CC;
    float acc = 0.f;
#pragma unroll
    for (int j = lane; j < CC; j += 32) acc += wr[j] * ps[j];
    for (int o = 16; o > 0; o >>= 1) acc += __shfl_down_sync(0xffffffffu, acc, o);
    if (lane == 0) g_Wp[r] = acc;
}

// ---------------- K_t: t[b,n] = x[b,n,:] . Wp  (warp per row, float4) ----------------
__global__ void k_t(const float* __restrict__ x) {
    __shared__ float4 wp4[CC / 4];
    int tid = threadIdx.x;  // 256
    if (tid < CC / 4) wp4[tid] = ((const float4*)g_Wp)[tid];
    __syncthreads();
    int warp = tid >> 5, lane = tid & 31;
    int row = blockIdx.x * 8 + warp;           // [0, BB*NN)
    const float4* xr = (const float4*)(x + (size_t)row * CC);
    float4 v0 = xr[lane];
    float4 v1 = xr[lane + 32];
    float4 w0 = wp4[lane];
    float4 w1 = wp4[lane + 32];
    float acc = v0.x * w0.x + v0.y * w0.y + v0.z * w0.z + v0.w * w0.w
              + v1.x * w1.x + v1.y * w1.y + v1.z * w1.z + v1.w * w1.w;
    for (int o = 16; o > 0; o >>= 1) acc += __shfl_down_sync(0xffffffffu, acc, o);
    if (lane == 0) g_t[row] = acc;
}

// ---------------- K_bits: adj -> row bitmaps (no score; no deps) ----------------
// Bit layout: column = chunk*128 + 4*bitpos + u  for word u (0..3) of chunk (0..7).
__global__ void k_bits(const float* __restrict__ adj) {
    int tid = threadIdx.x;             // 256
    int b = blockIdx.x >> 7;           // 128 blocks per batch
    int chunk = blockIdx.x & 127;
    int warp = tid >> 5, lane = tid & 31;
    int n = chunk * 8 + warp;
    const float* ar = adj + ((size_t)b * NN + n) * NN;
    uint4* br = (uint4*)(g_bits + ((size_t)(b * NN) + n) * 32);
#pragma unroll
    for (int c = 0; c < 8; c++) {
        float4 v = *(const float4*)(ar + c * 128 + lane * 4);
        unsigned b0 = __ballot_sync(0xffffffffu, v.x != 0.0f);
        unsigned b1 = __ballot_sync(0xffffffffu, v.y != 0.0f);
        unsigned b2 = __ballot_sync(0xffffffffu, v.z != 0.0f);
        unsigned b3 = __ballot_sync(0xffffffffu, v.w != 0.0f);
        if (lane == 0) br[c] = make_uint4(b0, b1, b2, b3);
    }
}

// ---------------- K_y: warp per node, lane per bitmap word (full chip) ----------------
__global__ void k_y() {
    int b = blockIdx.y;
    int tid = threadIdx.x;             // 1024
    __shared__ float st[NN];
    st[tid] = g_t[b * NN + tid];
    __syncthreads();
    int warp = tid >> 5, lane = tid & 31;
    int n = blockIdx.x * 32 + warp;
    unsigned w = g_bits[((size_t)(b * NN) + n) * 32 + lane];
    int base = (lane >> 2) * 128 + (lane & 3);   // word -> chunk c=lane>>2, u=lane&3
    float acc = 0.f;
    while (w) {
        int L = __ffs(w) - 1;
        w &= w - 1;
        acc += st[base + 4 * L];
    }
    for (int o = 16; o > 0; o >>= 1) acc += __shfl_down_sync(0xffffffffu, acc, o);
    if (lane == 0) g_y[b * NN + n] = (acc + g_scal[1]) * g_scal[0];
}

// ---------------- K_rank: u64 keys, 16 subs per i (grid 16x16, one full wave) ----------------
__global__ void k_rank(const int* __restrict__ mask,
                       const int* __restrict__ n_nodes,
                       float* __restrict__ out_mask) {
    int b = blockIdx.y;
    __shared__ unsigned long long ks[NN];
    int t = threadIdx.x;               // 1024
    int mt = mask[b * NN + t];
    float yv = g_y[b * NN + t];
    unsigned u = __float_as_uint(yv);
    u = (u & 0x80000000u) ? ~u : (u | 0x80000000u);  // monotone float->uint
    ks[t] = mt ? ((((unsigned long long)u) << 10) | (unsigned)t)
               : 0xFFFFFFFFFFFFFFFFull;
    __syncthreads();
    int i   = blockIdx.x * 64 + (t >> 4);
    int sub = t & 15;
    unsigned long long ki = ks[i];
    const ulonglong2* ks2 = (const ulonglong2*)ks;
    int r = 0;
#pragma unroll 8
    for (int k = 0; k < 32; k++) {
        ulonglong2 v = ks2[sub + 16 * k];
        r += (v.x < ki) ? 1 : 0;
        r += (v.y < ki) ? 1 : 0;
    }
    r += __shfl_down_sync(0xffffffffu, r, 8, 16);
    r += __shfl_down_sync(0xffffffffu, r, 4, 16);
    r += __shfl_down_sync(0xffffffffu, r, 2, 16);
    r += __shfl_down_sync(0xffffffffu, r, 1, 16);
    if (sub == 0) {
        int mi = mask[b * NN + i];
        int nrem = (int)((float)n_nodes[b] * 0.5f);   // (1 - POOL_RATIO)
        int nm = (mi != 0 && r >= nrem) ? 1 : 0;
        g_mf[b * NN + i] = (float)nm;
        out_mask[b * NN + i] = (float)nm;
    }
}

// ---------------- K_compact: warp-scan -> live list + dead list ----------------
__global__ void k_compact(const int* __restrict__ n_nodes, float* __restrict__ out_nn) {
    int b = blockIdx.x;
    int i = threadIdx.x;               // 1024
    int lane = i & 31, w = i >> 5;
    int nm = (int)g_mf[b * NN + i];
    unsigned ball = __ballot_sync(0xffffffffu, nm != 0);
    int wpre = __popc(ball & ((1u << lane) - 1u));
    __shared__ int wsum[32];
    if (lane == 0) wsum[w] = __popc(ball);
    __syncthreads();
    if (w == 0) {
        int orig = wsum[lane];
        int v = orig;
        for (int o = 1; o < 32; o <<= 1) {
            int u = __shfl_up_sync(0xffffffffu, v, o);
            if (lane >= o) v += u;
        }
        wsum[lane] = v - orig;   // exclusive
    }
    __syncthreads();
    int excl = wsum[w] + wpre;
    if (nm) g_rows[b * NN + excl] = i;
    else    g_dead[b * NN + (i - excl)] = i;
    if (i == NN - 1) {
        int tot = excl + nm;
        g_nrows[b] = tot;
        g_ndead[b] = NN - tot;
        int nrem = (int)((float)n_nodes[b] * 0.5f);
        out_nn[b] = (float)(n_nodes[b] - nrem);
    }
}

// ---------------- K_gather: per-row bitmap decoded ONCE to smem indices ----------------
__global__ __launch_bounds__(256) void k_gather(const float* __restrict__ x) {
    int b = blockIdx.y;
    int nrows = g_nrows[b];
    if (blockIdx.x * 4 >= nrows) return;
    int tid = threadIdx.x;
    int sub = tid >> 6;        // row within block
    int ct  = tid & 63;        // float4 channel group
    int pos = blockIdx.x * 4 + sub;
    bool active = pos < nrows;

    __shared__ unsigned short sidx[4][256];
    __shared__ int scnt[4];

    // decode: first warp of each row group (ct<32), one bitmap word per lane
    if (active && ct < 32) {
        int row = g_rows[b * NN + pos];
        unsigned w = g_bits[((size_t)(b * NN) + row) * 32 + ct];
        int cnt = __popc(w);
        int inc = cnt;
        for (int o = 1; o < 32; o <<= 1) {
            int v = __shfl_up_sync(0xffffffffu, inc, o);
            if (ct >= o) inc += v;
        }
        int start = inc - cnt;
        int base = (ct >> 2) * 128 + (ct & 3);
        while (w) {
            int L = __ffs(w) - 1;
            w &= w - 1;
            sidx[sub][start++] = (unsigned short)(base + 4 * L);
        }
        if (ct == 31) scnt[sub] = inc;
    }
    __syncthreads();
    if (!active) return;

    int cnt = scnt[sub];
    const float* xb = x + (size_t)b * NN * CC + ct * 4;
    float4 a0 = make_float4(0.f, 0.f, 0.f, 0.f);
    float4 a1 = make_float4(0.f, 0.f, 0.f, 0.f);
    float4 a2 = make_float4(0.f, 0.f, 0.f, 0.f);
    float4 a3 = make_float4(0.f, 0.f, 0.f, 0.f);
    int t = 0;
    for (; t + 4 <= cnt; t += 4) {
        float4 v0 = *(const float4*)(xb + (int)sidx[sub][t] * CC);
        float4 v1 = *(const float4*)(xb + (int)sidx[sub][t + 1] * CC);
        float4 v2 = *(const float4*)(xb + (int)sidx[sub][t + 2] * CC);
        float4 v3 = *(const float4*)(xb + (int)sidx[sub][t + 3] * CC);
        a0.x += v0.x; a0.y += v0.y; a0.z += v0.z; a0.w += v0.w;
        a1.x += v1.x; a1.y += v1.y; a1.z += v1.z; a1.w += v1.w;
        a2.x += v2.x; a2.y += v2.y; a2.z += v2.z; a2.w += v2.w;
        a3.x += v3.x; a3.y += v3.y; a3.z += v3.z; a3.w += v3.w;
    }
    for (; t < cnt; t++) {
        float4 v = *(const float4*)(xb + (int)sidx[sub][t] * CC);
        a0.x += v.x; a0.y += v.y; a0.z += v.z; a0.w += v.w;
    }
    float4 r;
    r.x = (a0.x + a1.x) + (a2.x + a3.x);
    r.y = (a0.y + a1.y) + (a2.y + a3.y);
    r.z = (a0.z + a1.z) + (a2.z + a3.z);
    r.w = (a0.w + a1.w) + (a2.w + a3.w);
    *(float4*)(g_gc + ((size_t)b * NN + pos) * CC + ct * 4) = r;
}

// ---------------- K_gemm: tf32 MMA, 3-term split, dead-row zeroing folded in ----------------
#define GM 128
#define GN 128
#define GK 16
#define AP 20    // A-tile k pitch (floats): conflict-free fragment loads
#define BPD 136  // B-tile n pitch

__global__ __launch_bounds__(256) void k_gemm(const float* __restrict__ W,
                                              const float* __restrict__ bvec,
                                              float* __restrict__ out_x) {
    __shared__ float Ah[GM][AP], Al[GM][AP];
    __shared__ float Bh[GK][BPD], Bl[GK][BPD];
    __shared__ float bs[GN];
    int b = blockIdx.z;
    int nrows = g_nrows[b];
    int row0 = blockIdx.x * GM;
    int col0 = blockIdx.y * GN;
    int tid = threadIdx.x;
    int lane = tid & 31, warp = tid >> 5;
    int wm = warp & 3, wn = warp >> 2;       // 4 M-warps x 2 N-warps
    int gid = lane >> 2, tig = lane & 3;

    if (tid < GN) bs[tid] = bvec[col0 + tid];

    float acc[2][8][4];
#pragma unroll
    for (int i = 0; i < 2; i++)
#pragma unroll
        for (int j = 0; j < 8; j++)
#pragma unroll
            for (int k = 0; k < 4; k++) acc[i][j][k] = 0.f;

    if (row0 < nrows) {
        int rows_in = nrows - row0; if (rows_in > GM) rows_in = GM;
        const float* A = g_gc + ((size_t)b * NN + row0) * CC;
        for (int kt = 0; kt < CC; kt += GK) {
#pragma unroll
            for (int u = 0; u < 2; u++) {
                int idx = tid + u * 256;
                int m = idx >> 2, k4 = idx & 3;
                float4 v = (m < rows_in)
                               ? *(const float4*)(A + (size_t)m * CC + kt + k4 * 4)
                               : make_float4(0.f, 0.f, 0.f, 0.f);
                float4 h4, l4;
                tf32split(v.x, h4.x, l4.x);
                tf32split(v.y, h4.y, l4.y);
                tf32split(v.z, h4.z, l4.z);
                tf32split(v.w, h4.w, l4.w);
                *(float4*)&Ah[m][k4 * 4] = h4;
                *(float4*)&Al[m][k4 * 4] = l4;
                int k = idx >> 5, c4 = idx & 31;
                float4 w = *(const float4*)(W + (size_t)(kt + k) * CC + col0 + c4 * 4);
                tf32split(w.x, h4.x, l4.x);
                tf32split(w.y, h4.y, l4.y);
                tf32split(w.z, h4.z, l4.z);
                tf32split(w.w, h4.w, l4.w);
                *(float4*)&Bh[k][c4 * 4] = h4;
                *(float4*)&Bl[k][c4 * 4] = l4;
            }
            __syncthreads();
#pragma unroll
            for (int k8 = 0; k8 < GK; k8 += 8) {
                unsigned ah[2][4], al[2][4], bh[8][2], bl[8][2];
#pragma unroll
                for (int mt = 0; mt < 2; mt++) {
                    int r = wm * 32 + mt * 16 + gid;
                    ah[mt][0] = __float_as_uint(Ah[r][k8 + tig]);
                    ah[mt][1] = __float_as_uint(Ah[r + 8][k8 + tig]);
                    ah[mt][2] = __float_as_uint(Ah[r][k8 + tig + 4]);
                    ah[mt][3] = __float_as_uint(Ah[r + 8][k8 + tig + 4]);
                    al[mt][0] = __float_as_uint(Al[r][k8 + tig]);
                    al[mt][1] = __float_as_uint(Al[r + 8][k8 + tig]);
                    al[mt][2] = __float_as_uint(Al[r][k8 + tig + 4]);
                    al[mt][3] = __float_as_uint(Al[r + 8][k8 + tig + 4]);
                }
#pragma unroll
                for (int nt = 0; nt < 8; nt++) {
                    int c = wn * 64 + nt * 8 + gid;
                    bh[nt][0] = __float_as_uint(Bh[k8 + tig][c]);
                    bh[nt][1] = __float_as_uint(Bh[k8 + tig + 4][c]);
                    bl[nt][0] = __float_as_uint(Bl[k8 + tig][c]);
                    bl[nt][1] = __float_as_uint(Bl[k8 + tig + 4][c]);
                }
#pragma unroll
                for (int mt = 0; mt < 2; mt++)
#pragma unroll
                    for (int nt = 0; nt < 8; nt++) {
                        MMA_TF32(acc[mt][nt], al[mt], bh[nt]);
                        MMA_TF32(acc[mt][nt], ah[mt], bl[nt]);
                        MMA_TF32(acc[mt][nt], ah[mt], bh[nt]);
                    }
            }
            __syncthreads();
        }
    }
    __syncthreads();   // bs visible for all paths (uniform)

#pragma unroll
    for (int mt = 0; mt < 2; mt++)
#pragma unroll
        for (int rh = 0; rh < 2; rh++) {
            int g = row0 + wm * 32 + mt * 16 + rh * 8 + gid;
            bool live = g < nrows;
            int node = live ? g_rows[b * NN + g] : g_dead[b * NN + g - nrows];
            float tval = live ? tanhf(g_y[b * NN + node]) : 0.f;
            float* orow = out_x + ((size_t)b * NN + node) * CC + col0 + wn * 64 + 2 * tig;
#pragma unroll
            for (int nt = 0; nt < 8; nt++) {
                float2 o;
                if (live) {
                    int c = wn * 64 + nt * 8 + 2 * tig;
                    o.x = (acc[mt][nt][rh * 2]     + bs[c])     * tval;
                    o.y = (acc[mt][nt][rh * 2 + 1] + bs[c + 1]) * tval;
                } else {
                    o.x = 0.f; o.y = 0.f;
                }
                *(float2*)(orow + nt * 8) = o;
            }
        }
}

// ---------------- K_adjout: dense bitmap expansion, 8 rows/block, full 1024 cols ----------------
__global__ __launch_bounds__(512) void k_adjout(float* __restrict__ out_adj) {
    int b = blockIdx.y;
    int tid = threadIdx.x;   // 512
    __shared__ float smf[NN];
    if (tid < 256) ((float4*)smf)[tid] = ((const float4*)(g_mf + b * NN))[tid];
    __syncthreads();
    int sub = tid >> 6, ct = tid & 63;
    int n = blockIdx.x * 8 + sub;
    float mfn = smf[n];
    const uint4* bwp = (const uint4*)(g_bits + ((size_t)(b * NN) + n) * 32);
    float4* orow = (float4*)(out_adj + ((size_t)b * NN + n) * NN);
#pragma unroll
    for (int u2 = 0; u2 < 4; u2++) {
        int cg = ct + u2 * 64;             // float4 column group 0..255
        uint4 bw = bwp[cg >> 5];           // chunk cg>>5 (0..7), words u0..u3
        int L = cg & 31;
        float4 mrow = ((const float4*)smf)[cg];   // mf for cols 4cg..4cg+3
        float4 o;
        o.x = ((bw.x >> L) & 1u) ? mfn * mrow.x : 0.f;
        o.y = ((bw.y >> L) & 1u) ? mfn * mrow.y : 0.f;
        o.z = ((bw.z >> L) & 1u) ? mfn * mrow.z : 0.f;
        o.w = ((bw.w >> L) & 1u) ? mfn * mrow.w : 0.f;
        orow[cg] = o;
    }
}

// ---------------- launch ----------------
extern "C" void kernel_launch(void* const* d_in, const int* in_sizes, int n_in,
                              void* d_out, int out_size) {
    const float* x    = (const float*)d_in[0];  // [B,N,C]
    const float* adj  = (const float*)d_in[1];  // [B,N,N]
    const int*   mask = (const int*)d_in[2];    // [B,N]
    const int*   nnod = (const int*)d_in[3];    // [B]
    const float* W    = (const float*)d_in[4];  // [C,C]
    const float* bv   = (const float*)d_in[5];  // [C]
    const float* pool = (const float*)d_in[6];  // [C,1]

    float* out = (float*)d_out;
    float* out_x    = out;                                   // B*N*C
    float* out_adj  = out + (size_t)BB * NN * CC;            // B*N*N
    float* out_mask = out_adj + (size_t)BB * NN * NN;        // B*N
    float* out_nn   = out_mask + (size_t)BB * NN;            // B

    // side stream + events (host-side resources only)
    cudaStream_t s2;
    cudaEvent_t e0, eT, eR, eJ;
    cudaStreamCreateWithFlags(&s2, cudaStreamNonBlocking);
    cudaEventCreateWithFlags(&e0, cudaEventDisableTiming);
    cudaEventCreateWithFlags(&eT, cudaEventDisableTiming);
    cudaEventCreateWithFlags(&eR, cudaEventDisableTiming);
    cudaEventCreateWithFlags(&eJ, cudaEventDisableTiming);

    // fork at t=0: s2 runs prep -> k_t while main runs the heavy k_bits
    cudaEventRecord(e0, 0);
    cudaStreamWaitEvent(s2, e0, 0);
    k_prep<<<33, 256, 0, s2>>>(W, bv, pool);
    k_t<<<(BB * NN) / 8, 256, 0, s2>>>(x);
    cudaEventRecord(eT, s2);

    k_bits<<<(BB * NN) / 8, 256>>>(adj);

    cudaStreamWaitEvent(0, eT, 0);   // join: k_y needs g_t, g_scal, g_bits
    k_y<<<dim3(32, BB), 1024>>>();
    k_rank<<<dim3(16, BB), 1024>>>(mask, nnod, out_mask);

    // fork: adjout needs only g_mf (rank) + g_bits
    cudaEventRecord(eR, 0);
    cudaStreamWaitEvent(s2, eR, 0);
    k_adjout<<<dim3(NN / 8, BB), 512, 0, s2>>>(out_adj);
    cudaEventRecord(eJ, s2);

    k_compact<<<BB, 1024>>>(nnod, out_nn);
    k_gather<<<dim3(NN / 4, BB), 256>>>(x);
    k_gemm<<<dim3(NN / GM, CC / GN, BB), 256>>>(W, bv, out_x);

    // join
    cudaStreamWaitEvent(0, eJ, 0);
}